// round 2
// baseline (speedup 1.0000x reference)
#include <cuda_runtime.h>
#include <math.h>

#define NB 16
#define NC 256
#define NT 4096
#define TT 64

#define XS_STRIDE 72
#define ZS_STRIDE 68
// smem floats: xs[256*72]=18432, zs[256*68]=17408, ws[4*2048]=8192
#define XS_F 18432
#define ZS_F 17408
#define WS_F 8192
#define SMEM_FLOATS (XS_F + ZS_F + WS_F)
#define SMEM_BYTES (SMEM_FLOATS * 4)

// Pre-transposed weights: [m][i][o], m = {wf_tap0, wf_tap1, wg_tap0, wg_tap1, w_res, w_skip}
__device__ float g_wt[6 * 256 * 256];

__global__ void prep_weights_k(const float* __restrict__ wf, const float* __restrict__ wg,
                               const float* __restrict__ wr, const float* __restrict__ wk) {
    int idx = blockIdx.x * 256 + threadIdx.x;  // idx = i*256 + o
    int i = idx >> 8, o = idx & 255;
    g_wt[0 * 65536 + idx] = wf[o * 512 + i * 2 + 0];
    g_wt[1 * 65536 + idx] = wf[o * 512 + i * 2 + 1];
    g_wt[2 * 65536 + idx] = wg[o * 512 + i * 2 + 0];
    g_wt[3 * 65536 + idx] = wg[o * 512 + i * 2 + 1];
    g_wt[4 * 65536 + idx] = wr[o * 256 + i];
    g_wt[5 * 65536 + idx] = wk[o * 256 + i];
}

__global__ __launch_bounds__(256, 1)
void wavenet_block_k(const float* __restrict__ x,
                     const float* __restrict__ b_f, const float* __restrict__ b_g,
                     const float* __restrict__ b_r, const float* __restrict__ b_k,
                     float* __restrict__ out_res, float* __restrict__ out_skip) {
    extern __shared__ float smem[];
    float* xs = smem;                 // [256][72]  x tile: col c = x[tb - 8 + c]
    float* zs = smem + XS_F;          // [256][68]  z tile
    float* ws = smem + XS_F + ZS_F;   // [4][8][256] weight k-tiles

    const int tid = threadIdx.x;
    const int bT = blockIdx.x * TT;
    const int bB = blockIdx.y;
    const int o0 = (tid >> 3) * 8;    // 32 o-groups of 8 channels
    const int t0 = (tid & 7) * 8;     // 8 t-groups of 8 timesteps

    const float* xbase = x + (size_t)bB * (NC * NT);

    // ---- Phase A: load x tile [256][72] (with 8-col causal halo, zero-padded) ----
    for (int idx = tid; idx < 256 * 18; idx += 256) {
        int row = idx / 18;
        int col = idx - row * 18;
        int gt = bT - 8 + col * 4;
        float4 v = make_float4(0.f, 0.f, 0.f, 0.f);
        if (gt >= 0) v = *(const float4*)(xbase + row * NT + gt);
        *(float4*)(xs + row * XS_STRIDE + col * 4) = v;
    }

    float accA[64], accB[64];
#pragma unroll
    for (int i = 0; i < 64; i++) { accA[i] = 0.f; accB[i] = 0.f; }

    // ---- Phase B: filter + gate dilated convs as GEMM over 256 in-channels ----
    for (int kk = 0; kk < 256; kk += 8) {
        __syncthreads();
        const float* src = g_wt + kk * 256;
#pragma unroll
        for (int m = 0; m < 4; m++) {
#pragma unroll
            for (int j = 0; j < 2; j++) {
                int id4 = j * 256 + tid;
                *(float4*)(ws + m * 2048 + id4 * 4) =
                    *(const float4*)(src + m * 65536 + id4 * 4);
            }
        }
        __syncthreads();
#pragma unroll
        for (int kt = 0; kt < 8; kt++) {
            const float* xr = xs + (kk + kt) * XS_STRIDE;
            float xv[16];
            *(float4*)(xv + 0)  = *(const float4*)(xr + t0);
            *(float4*)(xv + 4)  = *(const float4*)(xr + t0 + 4);
            *(float4*)(xv + 8)  = *(const float4*)(xr + t0 + 8);
            *(float4*)(xv + 12) = *(const float4*)(xr + t0 + 12);
            float wv[32];
            const float* wb = ws + kt * 256 + o0;
            *(float4*)(wv + 0)  = *(const float4*)(wb + 0);
            *(float4*)(wv + 4)  = *(const float4*)(wb + 4);
            *(float4*)(wv + 8)  = *(const float4*)(wb + 2048);
            *(float4*)(wv + 12) = *(const float4*)(wb + 2052);
            *(float4*)(wv + 16) = *(const float4*)(wb + 4096);
            *(float4*)(wv + 20) = *(const float4*)(wb + 4100);
            *(float4*)(wv + 24) = *(const float4*)(wb + 6144);
            *(float4*)(wv + 28) = *(const float4*)(wb + 6148);
#pragma unroll
            for (int a = 0; a < 8; a++) {
                float wf0 = wv[a], wf1 = wv[8 + a];
                float wg0 = wv[16 + a], wg1 = wv[24 + a];
#pragma unroll
                for (int b = 0; b < 8; b++) {
                    // tap0 hits x[t-8] (col t0+b), tap1 hits x[t] (col t0+b+8)
                    accA[a * 8 + b] += wf0 * xv[b] + wf1 * xv[8 + b];
                    accB[a * 8 + b] += wg0 * xv[b] + wg1 * xv[8 + b];
                }
            }
        }
    }

    // ---- Gated activation -> z in smem ----
    {
        float bfv[8], bgv[8];
#pragma unroll
        for (int a = 0; a < 8; a++) { bfv[a] = b_f[o0 + a]; bgv[a] = b_g[o0 + a]; }
#pragma unroll
        for (int a = 0; a < 8; a++) {
#pragma unroll
            for (int b4 = 0; b4 < 2; b4++) {
                float4 zv;
                float* zp = (float*)&zv;
#pragma unroll
                for (int e = 0; e < 4; e++) {
                    int b = b4 * 4 + e;
                    float f = tanhf(accA[a * 8 + b] + bfv[a]);
                    float gp = accB[a * 8 + b] + bgv[a];
                    float g = 1.0f / (1.0f + __expf(-gp));
                    zp[e] = f * g;
                }
                *(float4*)(zs + (o0 + a) * ZS_STRIDE + t0 + b4 * 4) = zv;
            }
        }
    }

#pragma unroll
    for (int i = 0; i < 64; i++) { accA[i] = 0.f; accB[i] = 0.f; }

    // ---- Phase C: both 1x1 convs as GEMM over z ----
    for (int kk = 0; kk < 256; kk += 8) {
        __syncthreads();   // first iteration also orders zs writes before reads
#pragma unroll
        for (int m = 0; m < 2; m++) {
#pragma unroll
            for (int j = 0; j < 2; j++) {
                int id4 = j * 256 + tid;
                *(float4*)(ws + m * 2048 + id4 * 4) =
                    *(const float4*)(g_wt + (4 + m) * 65536 + kk * 256 + id4 * 4);
            }
        }
        __syncthreads();
#pragma unroll
        for (int kt = 0; kt < 8; kt++) {
            const float* zr = zs + (kk + kt) * ZS_STRIDE;
            float zv[8];
            *(float4*)(zv + 0) = *(const float4*)(zr + t0);
            *(float4*)(zv + 4) = *(const float4*)(zr + t0 + 4);
            float wv2[16];
            const float* wb = ws + kt * 256 + o0;
            *(float4*)(wv2 + 0)  = *(const float4*)(wb + 0);
            *(float4*)(wv2 + 4)  = *(const float4*)(wb + 4);
            *(float4*)(wv2 + 8)  = *(const float4*)(wb + 2048);
            *(float4*)(wv2 + 12) = *(const float4*)(wb + 2052);
#pragma unroll
            for (int a = 0; a < 8; a++) {
                float wr_ = wv2[a], wk_ = wv2[8 + a];
#pragma unroll
                for (int b = 0; b < 8; b++) {
                    accA[a * 8 + b] += wr_ * zv[b];
                    accB[a * 8 + b] += wk_ * zv[b];
                }
            }
        }
    }

    // ---- Epilogue: res = x + conv_res + b_r ; skip = conv_skip + b_k ----
    {
        float brv[8], bkv[8];
#pragma unroll
        for (int a = 0; a < 8; a++) { brv[a] = b_r[o0 + a]; bkv[a] = b_k[o0 + a]; }
        float* rp = out_res  + ((size_t)bB * NC + o0) * NT + bT + t0;
        float* sp = out_skip + ((size_t)bB * NC + o0) * NT + bT + t0;
#pragma unroll
        for (int a = 0; a < 8; a++) {
#pragma unroll
            for (int b4 = 0; b4 < 2; b4++) {
                float4 xv4 = *(const float4*)(xs + (o0 + a) * XS_STRIDE + 8 + t0 + b4 * 4);
                float4 rv, sv;
                const float* xp = (const float*)&xv4;
                float* rr = (float*)&rv;
                float* ss = (float*)&sv;
#pragma unroll
                for (int e = 0; e < 4; e++) {
                    int b = b4 * 4 + e;
                    rr[e] = xp[e] + accA[a * 8 + b] + brv[a];
                    ss[e] = accB[a * 8 + b] + bkv[a];
                }
                *(float4*)(rp + a * NT + b4 * 4) = rv;
                *(float4*)(sp + a * NT + b4 * 4) = sv;
            }
        }
    }
}

extern "C" void kernel_launch(void* const* d_in, const int* in_sizes, int n_in,
                              void* d_out, int out_size) {
    const float* x  = (const float*)d_in[0];
    const float* wf = (const float*)d_in[1];
    const float* bf = (const float*)d_in[2];
    const float* wg = (const float*)d_in[3];
    const float* bg = (const float*)d_in[4];
    const float* wr = (const float*)d_in[5];
    const float* br = (const float*)d_in[6];
    const float* wk = (const float*)d_in[7];
    const float* bk = (const float*)d_in[8];
    float* out = (float*)d_out;

    cudaFuncSetAttribute(wavenet_block_k,
                         cudaFuncAttributeMaxDynamicSharedMemorySize, SMEM_BYTES);

    prep_weights_k<<<256, 256>>>(wf, wg, wr, wk);
    wavenet_block_k<<<dim3(NT / TT, NB), 256, SMEM_BYTES>>>(
        x, bf, bg, br, bk, out, out + (size_t)NB * NC * NT);
}

// round 3
// speedup vs baseline: 3.2914x; 3.2914x over previous
#include <cuda_runtime.h>
#include <cuda_bf16.h>
#include <math.h>
#include <stdint.h>

#define NB 16
#define NC 256
#define NT 4096
#define TT 64

// smem byte offsets: bf16 tiles, transposed [t][c], row stride 264 u16 (256 + 8 pad)
#define XS_H_OFF 0          // 72 rows * 264 * 2B = 38016
#define XS_L_OFF 38016
#define ZS_H_OFF 76032      // 64 rows * 264 * 2B = 33792
#define ZS_L_OFF 109824
#define SMEM_BYTES 143616
#define ROWU16 264
#define ROWU32 132

// Prepacked weights, exact mma.sync A-fragment per-lane order.
// uint4 index = ((slot*16 + kc)*16 + mtile)*32 + lane
// slot: 0 wf0_hi,1 wf0_lo,2 wf1_hi,3 wf1_lo,4 wg0_hi,5 wg0_lo,6 wg1_hi,7 wg1_lo,
//       8 wr_hi,9 wr_lo,10 wk_hi,11 wk_lo
__device__ uint4 g_wA4[12 * 16 * 16 * 32];

__device__ __forceinline__ uint32_t pack_bf16(float v0, float v1, int lo) {
    __nv_bfloat16 h0 = __float2bfloat16(v0);
    __nv_bfloat16 h1 = __float2bfloat16(v1);
    if (lo) {
        h0 = __float2bfloat16(v0 - __bfloat162float(h0));
        h1 = __float2bfloat16(v1 - __bfloat162float(h1));
    }
    uint16_t u0 = *reinterpret_cast<uint16_t*>(&h0);
    uint16_t u1 = *reinterpret_cast<uint16_t*>(&h1);
    return (uint32_t)u0 | ((uint32_t)u1 << 16);
}

__global__ void prep_wA_k(const float* __restrict__ wf, const float* __restrict__ wg,
                          const float* __restrict__ wr, const float* __restrict__ wk) {
    int idx = blockIdx.x * 256 + threadIdx.x;   // u32 index
    int reg  = idx & 3;
    int lane = (idx >> 2) & 31;
    int mtg  = (idx >> 7) & 15;
    int kc   = (idx >> 11) & 15;
    int slot = idx >> 15;
    int gq = lane >> 2, tq = lane & 3;
    int m  = mtg * 16 + gq + (reg & 1) * 8;
    int k0 = kc * 16 + 2 * tq + ((reg >> 1) & 1) * 8;
    int mat = slot >> 1, lo = slot & 1;
    float v0, v1;
    if      (mat == 0) { v0 = wf[m * 512 + k0 * 2];     v1 = wf[m * 512 + (k0 + 1) * 2]; }
    else if (mat == 1) { v0 = wf[m * 512 + k0 * 2 + 1]; v1 = wf[m * 512 + (k0 + 1) * 2 + 1]; }
    else if (mat == 2) { v0 = wg[m * 512 + k0 * 2];     v1 = wg[m * 512 + (k0 + 1) * 2]; }
    else if (mat == 3) { v0 = wg[m * 512 + k0 * 2 + 1]; v1 = wg[m * 512 + (k0 + 1) * 2 + 1]; }
    else if (mat == 4) { v0 = wr[m * 256 + k0];         v1 = wr[m * 256 + k0 + 1]; }
    else               { v0 = wk[m * 256 + k0];         v1 = wk[m * 256 + k0 + 1]; }
    reinterpret_cast<uint32_t*>(g_wA4)[idx] = pack_bf16(v0, v1, lo);
}

__device__ __forceinline__ void mma_bf16(float* d, const uint4& a, uint32_t b0, uint32_t b1) {
    asm volatile(
        "mma.sync.aligned.m16n8k16.row.col.f32.bf16.bf16.f32 "
        "{%0,%1,%2,%3}, {%4,%5,%6,%7}, {%8,%9}, {%0,%1,%2,%3};\n"
        : "+f"(d[0]), "+f"(d[1]), "+f"(d[2]), "+f"(d[3])
        : "r"(a.x), "r"(a.y), "r"(a.z), "r"(a.w), "r"(b0), "r"(b1));
}

__device__ __forceinline__ float fast_tanh(float v) {
    float y;
    asm("tanh.approx.f32 %0, %1;" : "=f"(y) : "f"(v));
    return y;
}
__device__ __forceinline__ float fast_sigmoid(float v) {
    return __fdividef(1.0f, 1.0f + __expf(-v));
}

__global__ __launch_bounds__(256, 1)
void wavenet_mma_k(const float* __restrict__ x,
                   const float* __restrict__ b_f, const float* __restrict__ b_g,
                   const float* __restrict__ b_r, const float* __restrict__ b_k,
                   float* __restrict__ out_res, float* __restrict__ out_skip) {
    extern __shared__ char sm[];
    __nv_bfloat16* xsH = (__nv_bfloat16*)(sm + XS_H_OFF);
    __nv_bfloat16* xsL = (__nv_bfloat16*)(sm + XS_L_OFF);
    __nv_bfloat16* zsH = (__nv_bfloat16*)(sm + ZS_H_OFF);
    __nv_bfloat16* zsL = (__nv_bfloat16*)(sm + ZS_L_OFF);

    const int tid  = threadIdx.x;
    const int warp = tid >> 5, lane = tid & 31;
    const int g = lane >> 2, t = lane & 3;
    const int bT = blockIdx.x * TT;
    const int bB = blockIdx.y;

    const float* xb = x + (size_t)bB * NC * NT;

    // ---- Phase A: load x tile, split into bf16 hi/lo, store transposed [t][c] ----
    // rows t' = 0..71 correspond to global t = bT - 8 + t'
    for (int it = 0; it < 18; it++) {
        int idx = it * 256 + tid;
        int row = idx / 18;           // channel 0..255
        int c   = idx - row * 18;     // float4 index along time
        int gt  = bT - 8 + c * 4;
        float4 v = make_float4(0.f, 0.f, 0.f, 0.f);
        if (gt >= 0) v = *(const float4*)(xb + row * NT + gt);
#pragma unroll
        for (int e = 0; e < 4; e++) {
            float val = (&v.x)[e];
            __nv_bfloat16 h = __float2bfloat16(val);
            __nv_bfloat16 l = __float2bfloat16(val - __bfloat162float(h));
            int tp = c * 4 + e;
            xsH[tp * ROWU16 + row] = h;
            xsL[tp * ROWU16 + row] = l;
        }
    }
    __syncthreads();

    float accP[2][8][4], accQ[2][8][4];
#pragma unroll
    for (int i = 0; i < 2; i++)
#pragma unroll
        for (int j = 0; j < 8; j++)
#pragma unroll
            for (int e = 0; e < 4; e++) { accP[i][j][e] = 0.f; accQ[i][j][e] = 0.f; }

    const uint4* wA4 = g_wA4;
    const uint32_t* xh = (const uint32_t*)xsH + g * ROWU32 + t;
    const uint32_t* xl = (const uint32_t*)xsL + g * ROWU32 + t;

    // ---- Phase B: dilated convs (filter + gate), K = 256, 2 taps, 3-way bf16 split ----
    for (int kc = 0; kc < 16; kc++) {
        uint32_t bh[9][2], bl[9][2];
#pragma unroll
        for (int rg = 0; rg < 9; rg++) {
            int off = rg * (8 * ROWU32) + kc * 8;
            bh[rg][0] = xh[off]; bh[rg][1] = xh[off + 4];
            bl[rg][0] = xl[off]; bl[rg][1] = xl[off + 4];
        }
#pragma unroll
        for (int mt = 0; mt < 2; mt++) {
            int mtg = warp * 2 + mt;
#pragma unroll
            for (int mg = 0; mg < 4; mg++) {       // 0:wf0 1:wf1 2:wg0 3:wg1
                uint4 ah = wA4[(((2 * mg    ) * 16 + kc) * 16 + mtg) * 32 + lane];
                uint4 al = wA4[(((2 * mg + 1) * 16 + kc) * 16 + mtg) * 32 + lane];
                int ro = mg & 1;                   // tap1 reads x[t], rowgroup +1
#pragma unroll
                for (int nt = 0; nt < 8; nt++) {
                    float* d = (mg < 2) ? accP[mt][nt] : accQ[mt][nt];
                    uint32_t h0 = bh[nt + ro][0], h1 = bh[nt + ro][1];
                    uint32_t l0 = bl[nt + ro][0], l1 = bl[nt + ro][1];
                    mma_bf16(d, ah, h0, h1);
                    mma_bf16(d, ah, l0, l1);
                    mma_bf16(d, al, h0, h1);
                }
            }
        }
    }

    // ---- Gated activation -> z (bf16 hi/lo, transposed [t][o]) ----
#pragma unroll
    for (int mt = 0; mt < 2; mt++) {
        int m0 = warp * 32 + mt * 16 + g;
        int m1 = m0 + 8;
        float bf0 = b_f[m0], bf1 = b_f[m1];
        float bg0 = b_g[m0], bg1 = b_g[m1];
#pragma unroll
        for (int nt = 0; nt < 8; nt++) {
            int n0 = nt * 8 + 2 * t;
            float z00 = fast_tanh(accP[mt][nt][0] + bf0) * fast_sigmoid(accQ[mt][nt][0] + bg0);
            float z01 = fast_tanh(accP[mt][nt][1] + bf0) * fast_sigmoid(accQ[mt][nt][1] + bg0);
            float z10 = fast_tanh(accP[mt][nt][2] + bf1) * fast_sigmoid(accQ[mt][nt][2] + bg1);
            float z11 = fast_tanh(accP[mt][nt][3] + bf1) * fast_sigmoid(accQ[mt][nt][3] + bg1);
            __nv_bfloat16 h;
            h = __float2bfloat16(z00); zsH[n0 * ROWU16 + m0] = h;
            zsL[n0 * ROWU16 + m0] = __float2bfloat16(z00 - __bfloat162float(h));
            h = __float2bfloat16(z01); zsH[(n0 + 1) * ROWU16 + m0] = h;
            zsL[(n0 + 1) * ROWU16 + m0] = __float2bfloat16(z01 - __bfloat162float(h));
            h = __float2bfloat16(z10); zsH[n0 * ROWU16 + m1] = h;
            zsL[n0 * ROWU16 + m1] = __float2bfloat16(z10 - __bfloat162float(h));
            h = __float2bfloat16(z11); zsH[(n0 + 1) * ROWU16 + m1] = h;
            zsL[(n0 + 1) * ROWU16 + m1] = __float2bfloat16(z11 - __bfloat162float(h));
        }
    }
    __syncthreads();

#pragma unroll
    for (int i = 0; i < 2; i++)
#pragma unroll
        for (int j = 0; j < 8; j++)
#pragma unroll
            for (int e = 0; e < 4; e++) { accP[i][j][e] = 0.f; accQ[i][j][e] = 0.f; }

    const uint32_t* zh = (const uint32_t*)zsH + g * ROWU32 + t;
    const uint32_t* zl = (const uint32_t*)zsL + g * ROWU32 + t;

    // ---- Phase C: both 1x1 convs over z, K = 256, 3-way split ----
    for (int kc = 0; kc < 16; kc++) {
        uint32_t bh[8][2], bl[8][2];
#pragma unroll
        for (int rg = 0; rg < 8; rg++) {
            int off = rg * (8 * ROWU32) + kc * 8;
            bh[rg][0] = zh[off]; bh[rg][1] = zh[off + 4];
            bl[rg][0] = zl[off]; bl[rg][1] = zl[off + 4];
        }
#pragma unroll
        for (int mt = 0; mt < 2; mt++) {
            int mtg = warp * 2 + mt;
#pragma unroll
            for (int mg = 0; mg < 2; mg++) {       // 0: w_res -> accP, 1: w_skip -> accQ
                int sh = 8 + 2 * mg;
                uint4 ah = wA4[(((sh    ) * 16 + kc) * 16 + mtg) * 32 + lane];
                uint4 al = wA4[(((sh + 1) * 16 + kc) * 16 + mtg) * 32 + lane];
#pragma unroll
                for (int nt = 0; nt < 8; nt++) {
                    float* d = (mg == 0) ? accP[mt][nt] : accQ[mt][nt];
                    uint32_t h0 = bh[nt][0], h1 = bh[nt][1];
                    uint32_t l0 = bl[nt][0], l1 = bl[nt][1];
                    mma_bf16(d, ah, h0, h1);
                    mma_bf16(d, ah, l0, l1);
                    mma_bf16(d, al, h0, h1);
                }
            }
        }
    }

    // ---- Epilogue: res = x + P + b_r ; skip = Q + b_k ----
#pragma unroll
    for (int mt = 0; mt < 2; mt++) {
        int m0 = warp * 32 + mt * 16 + g;
        int m1 = m0 + 8;
        float br0 = b_r[m0], br1 = b_r[m1];
        float bk0 = b_k[m0], bk1 = b_k[m1];
        float* rp0 = out_res  + ((size_t)bB * NC + m0) * NT + bT;
        float* rp1 = out_res  + ((size_t)bB * NC + m1) * NT + bT;
        float* sp0 = out_skip + ((size_t)bB * NC + m0) * NT + bT;
        float* sp1 = out_skip + ((size_t)bB * NC + m1) * NT + bT;
        const float* xr0 = xb + (size_t)m0 * NT + bT;
        const float* xr1 = xb + (size_t)m1 * NT + bT;
#pragma unroll
        for (int nt = 0; nt < 8; nt++) {
            int n0 = nt * 8 + 2 * t;
            float2 xv0 = *(const float2*)(xr0 + n0);
            float2 xv1 = *(const float2*)(xr1 + n0);
            float2 rv0 = make_float2(xv0.x + accP[mt][nt][0] + br0,
                                     xv0.y + accP[mt][nt][1] + br0);
            float2 rv1 = make_float2(xv1.x + accP[mt][nt][2] + br1,
                                     xv1.y + accP[mt][nt][3] + br1);
            float2 sv0 = make_float2(accQ[mt][nt][0] + bk0, accQ[mt][nt][1] + bk0);
            float2 sv1 = make_float2(accQ[mt][nt][2] + bk1, accQ[mt][nt][3] + bk1);
            *(float2*)(rp0 + n0) = rv0;
            *(float2*)(rp1 + n0) = rv1;
            *(float2*)(sp0 + n0) = sv0;
            *(float2*)(sp1 + n0) = sv1;
        }
    }
}

extern "C" void kernel_launch(void* const* d_in, const int* in_sizes, int n_in,
                              void* d_out, int out_size) {
    const float* x  = (const float*)d_in[0];
    const float* wf = (const float*)d_in[1];
    const float* bf = (const float*)d_in[2];
    const float* wg = (const float*)d_in[3];
    const float* bg = (const float*)d_in[4];
    const float* wr = (const float*)d_in[5];
    const float* br = (const float*)d_in[6];
    const float* wk = (const float*)d_in[7];
    const float* bk = (const float*)d_in[8];
    float* out = (float*)d_out;

    cudaFuncSetAttribute(wavenet_mma_k,
                         cudaFuncAttributeMaxDynamicSharedMemorySize, SMEM_BYTES);

    prep_wA_k<<<1536, 256>>>(wf, wg, wr, wk);
    wavenet_mma_k<<<dim3(NT / TT, NB), 256, SMEM_BYTES>>>(
        x, bf, bg, br, bk, out, out + (size_t)NB * NC * NT);
}

// round 4
// speedup vs baseline: 3.3172x; 1.0078x over previous
#include <cuda_runtime.h>
#include <cuda_bf16.h>
#include <math.h>
#include <stdint.h>

#define NB 16
#define NC 256
#define NT 4096
#define TT 64

// smem byte offsets: bf16 tiles, transposed [t][c], row stride 264 u16 (256 + 8 pad)
#define XS_H_OFF 0          // 72 rows * 264 * 2B = 38016
#define XS_L_OFF 38016
#define ZS_H_OFF 76032      // 64 rows * 264 * 2B = 33792
#define ZS_L_OFF 109824
#define SMEM_BYTES 143616
#define ROWU16 264
#define ROWU32 132

// Prepacked weights, exact mma.sync A-fragment per-lane order.
// uint4 index = ((slot*16 + kc)*16 + mtile)*32 + lane
// slot: 0 wf0_hi,1 wf0_lo,2 wf1_hi,3 wf1_lo,4 wg0_hi,5 wg0_lo,6 wg1_hi,7 wg1_lo,
//       8 wr_hi,9 wr_lo,10 wk_hi,11 wk_lo
__device__ uint4 g_wA4[12 * 16 * 16 * 32];

__device__ __forceinline__ uint32_t pack_bf16(float v0, float v1, int lo) {
    __nv_bfloat16 h0 = __float2bfloat16(v0);
    __nv_bfloat16 h1 = __float2bfloat16(v1);
    if (lo) {
        h0 = __float2bfloat16(v0 - __bfloat162float(h0));
        h1 = __float2bfloat16(v1 - __bfloat162float(h1));
    }
    uint16_t u0 = *reinterpret_cast<uint16_t*>(&h0);
    uint16_t u1 = *reinterpret_cast<uint16_t*>(&h1);
    return (uint32_t)u0 | ((uint32_t)u1 << 16);
}

__global__ void prep_wA_k(const float* __restrict__ wf, const float* __restrict__ wg,
                          const float* __restrict__ wr, const float* __restrict__ wk) {
    int idx = blockIdx.x * 256 + threadIdx.x;   // u32 index
    int reg  = idx & 3;
    int lane = (idx >> 2) & 31;
    int mtg  = (idx >> 7) & 15;
    int kc   = (idx >> 11) & 15;
    int slot = idx >> 15;
    int gq = lane >> 2, tq = lane & 3;
    int m  = mtg * 16 + gq + (reg & 1) * 8;
    int k0 = kc * 16 + 2 * tq + ((reg >> 1) & 1) * 8;
    int mat = slot >> 1, lo = slot & 1;
    float v0, v1;
    if      (mat == 0) { v0 = wf[m * 512 + k0 * 2];     v1 = wf[m * 512 + (k0 + 1) * 2]; }
    else if (mat == 1) { v0 = wf[m * 512 + k0 * 2 + 1]; v1 = wf[m * 512 + (k0 + 1) * 2 + 1]; }
    else if (mat == 2) { v0 = wg[m * 512 + k0 * 2];     v1 = wg[m * 512 + (k0 + 1) * 2]; }
    else if (mat == 3) { v0 = wg[m * 512 + k0 * 2 + 1]; v1 = wg[m * 512 + (k0 + 1) * 2 + 1]; }
    else if (mat == 4) { v0 = wr[m * 256 + k0];         v1 = wr[m * 256 + k0 + 1]; }
    else               { v0 = wk[m * 256 + k0];         v1 = wk[m * 256 + k0 + 1]; }
    reinterpret_cast<uint32_t*>(g_wA4)[idx] = pack_bf16(v0, v1, lo);
}

__device__ __forceinline__ void mma_bf16(float* d, const uint4& a, uint32_t b0, uint32_t b1) {
    asm volatile(
        "mma.sync.aligned.m16n8k16.row.col.f32.bf16.bf16.f32 "
        "{%0,%1,%2,%3}, {%4,%5,%6,%7}, {%8,%9}, {%0,%1,%2,%3};\n"
        : "+f"(d[0]), "+f"(d[1]), "+f"(d[2]), "+f"(d[3])
        : "r"(a.x), "r"(a.y), "r"(a.z), "r"(a.w), "r"(b0), "r"(b1));
}

__device__ __forceinline__ float fast_tanh(float v) {
    float y;
    asm("tanh.approx.f32 %0, %1;" : "=f"(y) : "f"(v));
    return y;
}
__device__ __forceinline__ float fast_sigmoid(float v) {
    return __fdividef(1.0f, 1.0f + __expf(-v));
}

__global__ __launch_bounds__(256, 1)
void wavenet_mma_k(const float* __restrict__ x,
                   const float* __restrict__ b_f, const float* __restrict__ b_g,
                   const float* __restrict__ b_r, const float* __restrict__ b_k,
                   float* __restrict__ out_res, float* __restrict__ out_skip) {
    extern __shared__ char sm[];
    __nv_bfloat16* xsH = (__nv_bfloat16*)(sm + XS_H_OFF);
    __nv_bfloat16* xsL = (__nv_bfloat16*)(sm + XS_L_OFF);
    __nv_bfloat16* zsH = (__nv_bfloat16*)(sm + ZS_H_OFF);
    __nv_bfloat16* zsL = (__nv_bfloat16*)(sm + ZS_L_OFF);

    const int tid  = threadIdx.x;
    const int warp = tid >> 5, lane = tid & 31;
    const int g = lane >> 2, t = lane & 3;
    const int bT = blockIdx.x * TT;
    const int bB = blockIdx.y;

    const float* xb = x + (size_t)bB * NC * NT;

    // ---- Phase A: load x tile, split into bf16 hi/lo, store transposed [t][c] ----
    // rows t' = 0..71 correspond to global t = bT - 8 + t'
    for (int it = 0; it < 18; it++) {
        int idx = it * 256 + tid;
        int row = idx / 18;           // channel 0..255
        int c   = idx - row * 18;     // float4 index along time
        int gt  = bT - 8 + c * 4;
        float4 v = make_float4(0.f, 0.f, 0.f, 0.f);
        if (gt >= 0) v = *(const float4*)(xb + row * NT + gt);
#pragma unroll
        for (int e = 0; e < 4; e++) {
            float val = (&v.x)[e];
            __nv_bfloat16 h = __float2bfloat16(val);
            __nv_bfloat16 l = __float2bfloat16(val - __bfloat162float(h));
            int tp = c * 4 + e;
            xsH[tp * ROWU16 + row] = h;
            xsL[tp * ROWU16 + row] = l;
        }
    }
    __syncthreads();

    float accP[2][8][4], accQ[2][8][4];
#pragma unroll
    for (int i = 0; i < 2; i++)
#pragma unroll
        for (int j = 0; j < 8; j++)
#pragma unroll
            for (int e = 0; e < 4; e++) { accP[i][j][e] = 0.f; accQ[i][j][e] = 0.f; }

    const uint4* wA4 = g_wA4;
    const uint32_t* xh = (const uint32_t*)xsH + g * ROWU32 + t;
    const uint32_t* xl = (const uint32_t*)xsL + g * ROWU32 + t;

    // ---- Phase B: dilated convs (filter + gate), K = 256, 2 taps, 3-way bf16 split ----
    for (int kc = 0; kc < 16; kc++) {
        uint32_t bh[9][2], bl[9][2];
#pragma unroll
        for (int rg = 0; rg < 9; rg++) {
            int off = rg * (8 * ROWU32) + kc * 8;
            bh[rg][0] = xh[off]; bh[rg][1] = xh[off + 4];
            bl[rg][0] = xl[off]; bl[rg][1] = xl[off + 4];
        }
#pragma unroll
        for (int mt = 0; mt < 2; mt++) {
            int mtg = warp * 2 + mt;
#pragma unroll
            for (int mg = 0; mg < 4; mg++) {       // 0:wf0 1:wf1 2:wg0 3:wg1
                uint4 ah = wA4[(((2 * mg    ) * 16 + kc) * 16 + mtg) * 32 + lane];
                uint4 al = wA4[(((2 * mg + 1) * 16 + kc) * 16 + mtg) * 32 + lane];
                int ro = mg & 1;                   // tap1 reads x[t], rowgroup +1
#pragma unroll
                for (int nt = 0; nt < 8; nt++) {
                    float* d = (mg < 2) ? accP[mt][nt] : accQ[mt][nt];
                    uint32_t h0 = bh[nt + ro][0], h1 = bh[nt + ro][1];
                    uint32_t l0 = bl[nt + ro][0], l1 = bl[nt + ro][1];
                    mma_bf16(d, ah, h0, h1);
                    mma_bf16(d, ah, l0, l1);
                    mma_bf16(d, al, h0, h1);
                }
            }
        }
    }

    // ---- Gated activation -> z (bf16 hi/lo, transposed [t][o]) ----
#pragma unroll
    for (int mt = 0; mt < 2; mt++) {
        int m0 = warp * 32 + mt * 16 + g;
        int m1 = m0 + 8;
        float bf0 = b_f[m0], bf1 = b_f[m1];
        float bg0 = b_g[m0], bg1 = b_g[m1];
#pragma unroll
        for (int nt = 0; nt < 8; nt++) {
            int n0 = nt * 8 + 2 * t;
            float z00 = fast_tanh(accP[mt][nt][0] + bf0) * fast_sigmoid(accQ[mt][nt][0] + bg0);
            float z01 = fast_tanh(accP[mt][nt][1] + bf0) * fast_sigmoid(accQ[mt][nt][1] + bg0);
            float z10 = fast_tanh(accP[mt][nt][2] + bf1) * fast_sigmoid(accQ[mt][nt][2] + bg1);
            float z11 = fast_tanh(accP[mt][nt][3] + bf1) * fast_sigmoid(accQ[mt][nt][3] + bg1);
            __nv_bfloat16 h;
            h = __float2bfloat16(z00); zsH[n0 * ROWU16 + m0] = h;
            zsL[n0 * ROWU16 + m0] = __float2bfloat16(z00 - __bfloat162float(h));
            h = __float2bfloat16(z01); zsH[(n0 + 1) * ROWU16 + m0] = h;
            zsL[(n0 + 1) * ROWU16 + m0] = __float2bfloat16(z01 - __bfloat162float(h));
            h = __float2bfloat16(z10); zsH[n0 * ROWU16 + m1] = h;
            zsL[n0 * ROWU16 + m1] = __float2bfloat16(z10 - __bfloat162float(h));
            h = __float2bfloat16(z11); zsH[(n0 + 1) * ROWU16 + m1] = h;
            zsL[(n0 + 1) * ROWU16 + m1] = __float2bfloat16(z11 - __bfloat162float(h));
        }
    }
    __syncthreads();

#pragma unroll
    for (int i = 0; i < 2; i++)
#pragma unroll
        for (int j = 0; j < 8; j++)
#pragma unroll
            for (int e = 0; e < 4; e++) { accP[i][j][e] = 0.f; accQ[i][j][e] = 0.f; }

    const uint32_t* zh = (const uint32_t*)zsH + g * ROWU32 + t;
    const uint32_t* zl = (const uint32_t*)zsL + g * ROWU32 + t;

    // ---- Phase C: both 1x1 convs over z, K = 256, 3-way split ----
    for (int kc = 0; kc < 16; kc++) {
        uint32_t bh[8][2], bl[8][2];
#pragma unroll
        for (int rg = 0; rg < 8; rg++) {
            int off = rg * (8 * ROWU32) + kc * 8;
            bh[rg][0] = zh[off]; bh[rg][1] = zh[off + 4];
            bl[rg][0] = zl[off]; bl[rg][1] = zl[off + 4];
        }
#pragma unroll
        for (int mt = 0; mt < 2; mt++) {
            int mtg = warp * 2 + mt;
#pragma unroll
            for (int mg = 0; mg < 2; mg++) {       // 0: w_res -> accP, 1: w_skip -> accQ
                int sh = 8 + 2 * mg;
                uint4 ah = wA4[(((sh    ) * 16 + kc) * 16 + mtg) * 32 + lane];
                uint4 al = wA4[(((sh + 1) * 16 + kc) * 16 + mtg) * 32 + lane];
#pragma unroll
                for (int nt = 0; nt < 8; nt++) {
                    float* d = (mg == 0) ? accP[mt][nt] : accQ[mt][nt];
                    uint32_t h0 = bh[nt][0], h1 = bh[nt][1];
                    uint32_t l0 = bl[nt][0], l1 = bl[nt][1];
                    mma_bf16(d, ah, h0, h1);
                    mma_bf16(d, ah, l0, l1);
                    mma_bf16(d, al, h0, h1);
                }
            }
        }
    }

    // ---- Epilogue: res = x + P + b_r ; skip = Q + b_k ----
#pragma unroll
    for (int mt = 0; mt < 2; mt++) {
        int m0 = warp * 32 + mt * 16 + g;
        int m1 = m0 + 8;
        float br0 = b_r[m0], br1 = b_r[m1];
        float bk0 = b_k[m0], bk1 = b_k[m1];
        float* rp0 = out_res  + ((size_t)bB * NC + m0) * NT + bT;
        float* rp1 = out_res  + ((size_t)bB * NC + m1) * NT + bT;
        float* sp0 = out_skip + ((size_t)bB * NC + m0) * NT + bT;
        float* sp1 = out_skip + ((size_t)bB * NC + m1) * NT + bT;
        const float* xr0 = xb + (size_t)m0 * NT + bT;
        const float* xr1 = xb + (size_t)m1 * NT + bT;
#pragma unroll
        for (int nt = 0; nt < 8; nt++) {
            int n0 = nt * 8 + 2 * t;
            float2 xv0 = *(const float2*)(xr0 + n0);
            float2 xv1 = *(const float2*)(xr1 + n0);
            float2 rv0 = make_float2(xv0.x + accP[mt][nt][0] + br0,
                                     xv0.y + accP[mt][nt][1] + br0);
            float2 rv1 = make_float2(xv1.x + accP[mt][nt][2] + br1,
                                     xv1.y + accP[mt][nt][3] + br1);
            float2 sv0 = make_float2(accQ[mt][nt][0] + bk0, accQ[mt][nt][1] + bk0);
            float2 sv1 = make_float2(accQ[mt][nt][2] + bk1, accQ[mt][nt][3] + bk1);
            *(float2*)(rp0 + n0) = rv0;
            *(float2*)(rp1 + n0) = rv1;
            *(float2*)(sp0 + n0) = sv0;
            *(float2*)(sp1 + n0) = sv1;
        }
    }
}

extern "C" void kernel_launch(void* const* d_in, const int* in_sizes, int n_in,
                              void* d_out, int out_size) {
    const float* x  = (const float*)d_in[0];
    const float* wf = (const float*)d_in[1];
    const float* bf = (const float*)d_in[2];
    const float* wg = (const float*)d_in[3];
    const float* bg = (const float*)d_in[4];
    const float* wr = (const float*)d_in[5];
    const float* br = (const float*)d_in[6];
    const float* wk = (const float*)d_in[7];
    const float* bk = (const float*)d_in[8];
    float* out = (float*)d_out;

    cudaFuncSetAttribute(wavenet_mma_k,
                         cudaFuncAttributeMaxDynamicSharedMemorySize, SMEM_BYTES);

    prep_wA_k<<<1536, 256>>>(wf, wg, wr, wk);
    wavenet_mma_k<<<dim3(NT / TT, NB), 256, SMEM_BYTES>>>(
        x, bf, bg, br, bk, out, out + (size_t)NB * NC * NT);
}

// round 6
// speedup vs baseline: 7.6398x; 2.3031x over previous
#include <cuda_runtime.h>
#include <cuda_fp16.h>
#include <math.h>
#include <stdint.h>

#define NB 16
#define NC 256
#define NT 4096
#define TT 64

// smem: fp16 tiles, transposed [t][c], row stride 264 u16 (256 + 8 pad)
#define XS_OFF 0            // 72 rows * 264 * 2B = 38016
#define ZS_OFF 38016        // 64 rows * 264 * 2B = 33792
#define SMEM_BYTES 71808
#define ROWU16 264
#define ROWU32 132

// Prepacked fp16 weights, exact mma.sync A-fragment per-lane order.
// uint4 index = ((slot*16 + kc)*16 + mtile)*32 + lane
// slot: 0 wf_tap0, 1 wf_tap1, 2 wg_tap0, 3 wg_tap1, 4 w_res, 5 w_skip
__device__ uint4 g_wA4[6 * 16 * 16 * 32];

__device__ __forceinline__ uint32_t pack_f16(float v0, float v1) {
    __half h0 = __float2half(v0);
    __half h1 = __float2half(v1);
    uint16_t u0 = *reinterpret_cast<uint16_t*>(&h0);
    uint16_t u1 = *reinterpret_cast<uint16_t*>(&h1);
    return (uint32_t)u0 | ((uint32_t)u1 << 16);
}

__global__ void prep_wA_k(const float* __restrict__ wf, const float* __restrict__ wg,
                          const float* __restrict__ wr, const float* __restrict__ wk) {
    int idx = blockIdx.x * 256 + threadIdx.x;   // u32 index, 196608 total
    int reg  = idx & 3;
    int lane = (idx >> 2) & 31;
    int mtg  = (idx >> 7) & 15;
    int kc   = (idx >> 11) & 15;
    int slot = idx >> 15;
    int gq = lane >> 2, tq = lane & 3;
    int m  = mtg * 16 + gq + (reg & 1) * 8;
    int k0 = kc * 16 + 2 * tq + ((reg >> 1) & 1) * 8;
    float v0, v1;
    if      (slot == 0) { v0 = wf[m * 512 + k0 * 2];     v1 = wf[m * 512 + (k0 + 1) * 2]; }
    else if (slot == 1) { v0 = wf[m * 512 + k0 * 2 + 1]; v1 = wf[m * 512 + (k0 + 1) * 2 + 1]; }
    else if (slot == 2) { v0 = wg[m * 512 + k0 * 2];     v1 = wg[m * 512 + (k0 + 1) * 2]; }
    else if (slot == 3) { v0 = wg[m * 512 + k0 * 2 + 1]; v1 = wg[m * 512 + (k0 + 1) * 2 + 1]; }
    else if (slot == 4) { v0 = wr[m * 256 + k0];         v1 = wr[m * 256 + k0 + 1]; }
    else                { v0 = wk[m * 256 + k0];         v1 = wk[m * 256 + k0 + 1]; }
    reinterpret_cast<uint32_t*>(g_wA4)[idx] = pack_f16(v0, v1);
}

__device__ __forceinline__ void mma_f16(float* d, const uint4& a, uint32_t b0, uint32_t b1) {
    asm volatile(
        "mma.sync.aligned.m16n8k16.row.col.f32.f16.f16.f32 "
        "{%0,%1,%2,%3}, {%4,%5,%6,%7}, {%8,%9}, {%0,%1,%2,%3};\n"
        : "+f"(d[0]), "+f"(d[1]), "+f"(d[2]), "+f"(d[3])
        : "r"(a.x), "r"(a.y), "r"(a.z), "r"(a.w), "r"(b0), "r"(b1));
}

__device__ __forceinline__ float fast_tanh(float v) {
    float y;
    asm("tanh.approx.f32 %0, %1;" : "=f"(y) : "f"(v));
    return y;
}
__device__ __forceinline__ float fast_sigmoid(float v) {
    return __fdividef(1.0f, 1.0f + __expf(-v));
}

__global__ __launch_bounds__(256, 1)
void wavenet_mma_k(const float* __restrict__ x,
                   const float* __restrict__ b_f, const float* __restrict__ b_g,
                   const float* __restrict__ b_r, const float* __restrict__ b_k,
                   float* __restrict__ out_res, float* __restrict__ out_skip) {
    extern __shared__ char sm[];
    __half* xs = (__half*)(sm + XS_OFF);
    __half* zs = (__half*)(sm + ZS_OFF);

    const int tid  = threadIdx.x;
    const int warp = tid >> 5, lane = tid & 31;
    const int g = lane >> 2, t = lane & 3;
    const int bT = blockIdx.x * TT;
    const int bB = blockIdx.y;

    const float* xb = x + (size_t)bB * NC * NT;

    // ---- Phase A: load x tile, fp16, transposed [t][c]; rows t'=0..71 = bT-8+t' ----
    for (int it = 0; it < 18; it++) {
        int idx = it * 256 + tid;
        int row = idx / 18;           // channel
        int c   = idx - row * 18;     // float4 index along time
        int gt  = bT - 8 + c * 4;
        float4 v = make_float4(0.f, 0.f, 0.f, 0.f);
        if (gt >= 0) v = *(const float4*)(xb + row * NT + gt);
#pragma unroll
        for (int e = 0; e < 4; e++) {
            int tp = c * 4 + e;
            xs[tp * ROWU16 + row] = __float2half((&v.x)[e]);
        }
    }
    __syncthreads();

    float accP[2][8][4], accQ[2][8][4];
#pragma unroll
    for (int i = 0; i < 2; i++)
#pragma unroll
        for (int j = 0; j < 8; j++)
#pragma unroll
            for (int e = 0; e < 4; e++) { accP[i][j][e] = 0.f; accQ[i][j][e] = 0.f; }

    const uint4* wA4 = g_wA4;
    const uint32_t* xh = (const uint32_t*)xs + g * ROWU32 + t;

    // ---- Phase B: dilated convs (filter + gate), K=256, 2 taps, fp16 1-term ----
    for (int kc = 0; kc < 16; kc++) {
        uint32_t bh[9][2];
#pragma unroll
        for (int rg = 0; rg < 9; rg++) {
            int off = rg * (8 * ROWU32) + kc * 8;
            bh[rg][0] = xh[off]; bh[rg][1] = xh[off + 4];
        }
#pragma unroll
        for (int mt = 0; mt < 2; mt++) {
            int mtg = warp * 2 + mt;
#pragma unroll
            for (int mg = 0; mg < 4; mg++) {       // 0:wf0 1:wf1 2:wg0 3:wg1
                uint4 a = wA4[((mg * 16 + kc) * 16 + mtg) * 32 + lane];
                int ro = mg & 1;                   // tap1 reads x[t], rowgroup +1
#pragma unroll
                for (int nt = 0; nt < 8; nt++) {
                    float* d = (mg < 2) ? accP[mt][nt] : accQ[mt][nt];
                    mma_f16(d, a, bh[nt + ro][0], bh[nt + ro][1]);
                }
            }
        }
    }

    // ---- Gated activation -> z (fp16, transposed [t][o]) ----
#pragma unroll
    for (int mt = 0; mt < 2; mt++) {
        int m0 = warp * 32 + mt * 16 + g;
        int m1 = m0 + 8;
        float bf0 = b_f[m0], bf1 = b_f[m1];
        float bg0 = b_g[m0], bg1 = b_g[m1];
#pragma unroll
        for (int nt = 0; nt < 8; nt++) {
            int n0 = nt * 8 + 2 * t;
            float z00 = fast_tanh(accP[mt][nt][0] + bf0) * fast_sigmoid(accQ[mt][nt][0] + bg0);
            float z01 = fast_tanh(accP[mt][nt][1] + bf0) * fast_sigmoid(accQ[mt][nt][1] + bg0);
            float z10 = fast_tanh(accP[mt][nt][2] + bf1) * fast_sigmoid(accQ[mt][nt][2] + bg1);
            float z11 = fast_tanh(accP[mt][nt][3] + bf1) * fast_sigmoid(accQ[mt][nt][3] + bg1);
            zs[n0 * ROWU16 + m0]       = __float2half(z00);
            zs[(n0 + 1) * ROWU16 + m0] = __float2half(z01);
            zs[n0 * ROWU16 + m1]       = __float2half(z10);
            zs[(n0 + 1) * ROWU16 + m1] = __float2half(z11);
        }
    }
    __syncthreads();

#pragma unroll
    for (int i = 0; i < 2; i++)
#pragma unroll
        for (int j = 0; j < 8; j++)
#pragma unroll
            for (int e = 0; e < 4; e++) { accP[i][j][e] = 0.f; accQ[i][j][e] = 0.f; }

    const uint32_t* zh = (const uint32_t*)zs + g * ROWU32 + t;

    // ---- Phase C: both 1x1 convs over z, K=256, fp16 1-term ----
    for (int kc = 0; kc < 16; kc++) {
        uint32_t bh[8][2];
#pragma unroll
        for (int rg = 0; rg < 8; rg++) {
            int off = rg * (8 * ROWU32) + kc * 8;
            bh[rg][0] = zh[off]; bh[rg][1] = zh[off + 4];
        }
#pragma unroll
        for (int mt = 0; mt < 2; mt++) {
            int mtg = warp * 2 + mt;
#pragma unroll
            for (int mg = 0; mg < 2; mg++) {       // 0: w_res -> accP, 1: w_skip -> accQ
                uint4 a = wA4[(((4 + mg) * 16 + kc) * 16 + mtg) * 32 + lane];
#pragma unroll
                for (int nt = 0; nt < 8; nt++) {
                    float* d = (mg == 0) ? accP[mt][nt] : accQ[mt][nt];
                    mma_f16(d, a, bh[nt][0], bh[nt][1]);
                }
            }
        }
    }

    // ---- Epilogue: res = x + P + b_r ; skip = Q + b_k ----
#pragma unroll
    for (int mt = 0; mt < 2; mt++) {
        int m0 = warp * 32 + mt * 16 + g;
        int m1 = m0 + 8;
        float br0 = b_r[m0], br1 = b_r[m1];
        float bk0 = b_k[m0], bk1 = b_k[m1];
        float* rp0 = out_res  + ((size_t)bB * NC + m0) * NT + bT;
        float* rp1 = out_res  + ((size_t)bB * NC + m1) * NT + bT;
        float* sp0 = out_skip + ((size_t)bB * NC + m0) * NT + bT;
        float* sp1 = out_skip + ((size_t)bB * NC + m1) * NT + bT;
        const float* xr0 = xb + (size_t)m0 * NT + bT;
        const float* xr1 = xb + (size_t)m1 * NT + bT;
#pragma unroll
        for (int nt = 0; nt < 8; nt++) {
            int n0 = nt * 8 + 2 * t;
            float2 xv0 = *(const float2*)(xr0 + n0);
            float2 xv1 = *(const float2*)(xr1 + n0);
            float2 rv0 = make_float2(xv0.x + accP[mt][nt][0] + br0,
                                     xv0.y + accP[mt][nt][1] + br0);
            float2 rv1 = make_float2(xv1.x + accP[mt][nt][2] + br1,
                                     xv1.y + accP[mt][nt][3] + br1);
            float2 sv0 = make_float2(accQ[mt][nt][0] + bk0, accQ[mt][nt][1] + bk0);
            float2 sv1 = make_float2(accQ[mt][nt][2] + bk1, accQ[mt][nt][3] + bk1);
            *(float2*)(rp0 + n0) = rv0;
            *(float2*)(rp1 + n0) = rv1;
            *(float2*)(sp0 + n0) = sv0;
            *(float2*)(sp1 + n0) = sv1;
        }
    }
}

extern "C" void kernel_launch(void* const* d_in, const int* in_sizes, int n_in,
                              void* d_out, int out_size) {
    const float* x  = (const float*)d_in[0];
    const float* wf = (const float*)d_in[1];
    const float* bf = (const float*)d_in[2];
    const float* wg = (const float*)d_in[3];
    const float* bg = (const float*)d_in[4];
    const float* wr = (const float*)d_in[5];
    const float* br = (const float*)d_in[6];
    const float* wk = (const float*)d_in[7];
    const float* bk = (const float*)d_in[8];
    float* out = (float*)d_out;

    cudaFuncSetAttribute(wavenet_mma_k,
                         cudaFuncAttributeMaxDynamicSharedMemorySize, SMEM_BYTES);

    prep_wA_k<<<768, 256>>>(wf, wg, wr, wk);
    wavenet_mma_k<<<dim3(NT / TT, NB), 256, SMEM_BYTES>>>(
        x, bf, bg, br, bk, out, out + (size_t)NB * NC * NT);
}

// round 7
// speedup vs baseline: 7.9944x; 1.0464x over previous
#include <cuda_runtime.h>
#include <cuda_fp16.h>
#include <math.h>
#include <stdint.h>

#define NB 16
#define NC 256
#define NT 4096
#define TT 64

// smem: fp16 tiles, transposed [t][c], row stride 264 u16 (256 + 8 pad)
#define XS_OFF 0            // 72 rows * 264 * 2B = 38016
#define ZS_OFF 38016        // 64 rows * 264 * 2B = 33792
#define SMEM_BYTES 71808
#define ROWU16 264
#define ROWU32 132

// Prepacked fp16 weights, exact mma.sync A-fragment per-lane order.
// uint4 index = ((slot*16 + kc)*16 + mtile)*32 + lane
// slot: 0 wf_tap0, 1 wf_tap1, 2 wg_tap0, 3 wg_tap1, 4 w_res, 5 w_skip
__device__ uint4 g_wA4[6 * 16 * 16 * 32];

__device__ __forceinline__ uint32_t pack_f16(float v0, float v1) {
    __half h0 = __float2half(v0);
    __half h1 = __float2half(v1);
    uint16_t u0 = *reinterpret_cast<uint16_t*>(&h0);
    uint16_t u1 = *reinterpret_cast<uint16_t*>(&h1);
    return (uint32_t)u0 | ((uint32_t)u1 << 16);
}

__global__ void prep_wA_k(const float* __restrict__ wf, const float* __restrict__ wg,
                          const float* __restrict__ wr, const float* __restrict__ wk) {
    int idx = blockIdx.x * 256 + threadIdx.x;   // u32 index, 196608 total
    int reg  = idx & 3;
    int lane = (idx >> 2) & 31;
    int mtg  = (idx >> 7) & 15;
    int kc   = (idx >> 11) & 15;
    int slot = idx >> 15;
    int gq = lane >> 2, tq = lane & 3;
    int m  = mtg * 16 + gq + (reg & 1) * 8;
    int k0 = kc * 16 + 2 * tq + ((reg >> 1) & 1) * 8;
    float v0, v1;
    if      (slot == 0) { v0 = wf[m * 512 + k0 * 2];     v1 = wf[m * 512 + (k0 + 1) * 2]; }
    else if (slot == 1) { v0 = wf[m * 512 + k0 * 2 + 1]; v1 = wf[m * 512 + (k0 + 1) * 2 + 1]; }
    else if (slot == 2) { v0 = wg[m * 512 + k0 * 2];     v1 = wg[m * 512 + (k0 + 1) * 2]; }
    else if (slot == 3) { v0 = wg[m * 512 + k0 * 2 + 1]; v1 = wg[m * 512 + (k0 + 1) * 2 + 1]; }
    else if (slot == 4) { v0 = wr[m * 256 + k0];         v1 = wr[m * 256 + k0 + 1]; }
    else                { v0 = wk[m * 256 + k0];         v1 = wk[m * 256 + k0 + 1]; }
    reinterpret_cast<uint32_t*>(g_wA4)[idx] = pack_f16(v0, v1);
}

__device__ __forceinline__ void mma_f16(float* d, const uint4& a, uint32_t b0, uint32_t b1) {
    asm volatile(
        "mma.sync.aligned.m16n8k16.row.col.f32.f16.f16.f32 "
        "{%0,%1,%2,%3}, {%4,%5,%6,%7}, {%8,%9}, {%0,%1,%2,%3};\n"
        : "+f"(d[0]), "+f"(d[1]), "+f"(d[2]), "+f"(d[3])
        : "r"(a.x), "r"(a.y), "r"(a.z), "r"(a.w), "r"(b0), "r"(b1));
}

__device__ __forceinline__ float fast_tanh(float v) {
    float y;
    asm("tanh.approx.f32 %0, %1;" : "=f"(y) : "f"(v));
    return y;
}
__device__ __forceinline__ float fast_sigmoid(float v) {
    return __fdividef(1.0f, 1.0f + __expf(-v));
}

__global__ __launch_bounds__(512, 1)
void wavenet_mma_k(const float* __restrict__ x,
                   const float* __restrict__ b_f, const float* __restrict__ b_g,
                   const float* __restrict__ b_r, const float* __restrict__ b_k,
                   float* __restrict__ out_res, float* __restrict__ out_skip) {
    extern __shared__ char sm[];
    __half* xs = (__half*)(sm + XS_OFF);
    __half* zs = (__half*)(sm + ZS_OFF);

    const int tid  = threadIdx.x;
    const int warp = tid >> 5, lane = tid & 31;   // 16 warps, warp == mtile
    const int g = lane >> 2, t = lane & 3;
    const int bT = blockIdx.x * TT;
    const int bB = blockIdx.y;

    const float* xb = x + (size_t)bB * NC * NT;

    // ---- Phase A: load x tile, fp16, transposed [t][c]; rows t'=0..71 = bT-8+t' ----
    for (int it = 0; it < 9; it++) {
        int idx = it * 512 + tid;
        int row = idx / 18;           // channel
        int c   = idx - row * 18;     // float4 index along time
        int gt  = bT - 8 + c * 4;
        float4 v = make_float4(0.f, 0.f, 0.f, 0.f);
        if (gt >= 0) v = *(const float4*)(xb + row * NT + gt);
#pragma unroll
        for (int e = 0; e < 4; e++) {
            int tp = c * 4 + e;
            xs[tp * ROWU16 + row] = __float2half((&v.x)[e]);
        }
    }
    __syncthreads();

    float accP[8][4], accQ[8][4];
#pragma unroll
    for (int j = 0; j < 8; j++)
#pragma unroll
        for (int e = 0; e < 4; e++) { accP[j][e] = 0.f; accQ[j][e] = 0.f; }

    const uint4* wA4 = g_wA4;
    const uint32_t* xh = (const uint32_t*)xs + g * ROWU32 + t;

    // ---- Phase B: dilated convs (filter + gate), K=256, 2 taps, fp16 1-term ----
    for (int kc = 0; kc < 16; kc++) {
        uint32_t bh[9][2];
#pragma unroll
        for (int rg = 0; rg < 9; rg++) {
            int off = rg * (8 * ROWU32) + kc * 8;
            bh[rg][0] = xh[off]; bh[rg][1] = xh[off + 4];
        }
#pragma unroll
        for (int mg = 0; mg < 4; mg++) {       // 0:wf0 1:wf1 2:wg0 3:wg1
            uint4 a = wA4[((mg * 16 + kc) * 16 + warp) * 32 + lane];
            int ro = mg & 1;                   // tap1 reads x[t], rowgroup +1
#pragma unroll
            for (int nt = 0; nt < 8; nt++) {
                float* d = (mg < 2) ? accP[nt] : accQ[nt];
                mma_f16(d, a, bh[nt + ro][0], bh[nt + ro][1]);
            }
        }
    }

    // ---- Gated activation -> z (fp16, transposed [t][o]) ----
    {
        int m0 = warp * 16 + g;
        int m1 = m0 + 8;
        float bf0 = b_f[m0], bf1 = b_f[m1];
        float bg0 = b_g[m0], bg1 = b_g[m1];
#pragma unroll
        for (int nt = 0; nt < 8; nt++) {
            int n0 = nt * 8 + 2 * t;
            float z00 = fast_tanh(accP[nt][0] + bf0) * fast_sigmoid(accQ[nt][0] + bg0);
            float z01 = fast_tanh(accP[nt][1] + bf0) * fast_sigmoid(accQ[nt][1] + bg0);
            float z10 = fast_tanh(accP[nt][2] + bf1) * fast_sigmoid(accQ[nt][2] + bg1);
            float z11 = fast_tanh(accP[nt][3] + bf1) * fast_sigmoid(accQ[nt][3] + bg1);
            zs[n0 * ROWU16 + m0]       = __float2half(z00);
            zs[(n0 + 1) * ROWU16 + m0] = __float2half(z01);
            zs[n0 * ROWU16 + m1]       = __float2half(z10);
            zs[(n0 + 1) * ROWU16 + m1] = __float2half(z11);
        }
    }
    __syncthreads();

#pragma unroll
    for (int j = 0; j < 8; j++)
#pragma unroll
        for (int e = 0; e < 4; e++) { accP[j][e] = 0.f; accQ[j][e] = 0.f; }

    const uint32_t* zh = (const uint32_t*)zs + g * ROWU32 + t;

    // ---- Phase C: both 1x1 convs over z, K=256, fp16 1-term ----
    for (int kc = 0; kc < 16; kc++) {
        uint32_t bh[8][2];
#pragma unroll
        for (int rg = 0; rg < 8; rg++) {
            int off = rg * (8 * ROWU32) + kc * 8;
            bh[rg][0] = zh[off]; bh[rg][1] = zh[off + 4];
        }
#pragma unroll
        for (int mg = 0; mg < 2; mg++) {       // 0: w_res -> accP, 1: w_skip -> accQ
            uint4 a = wA4[(((4 + mg) * 16 + kc) * 16 + warp) * 32 + lane];
#pragma unroll
            for (int nt = 0; nt < 8; nt++) {
                float* d = (mg == 0) ? accP[nt] : accQ[nt];
                mma_f16(d, a, bh[nt][0], bh[nt][1]);
            }
        }
    }

    // ---- Epilogue: res = x + P + b_r ; skip = Q + b_k ----
    {
        int m0 = warp * 16 + g;
        int m1 = m0 + 8;
        float br0 = b_r[m0], br1 = b_r[m1];
        float bk0 = b_k[m0], bk1 = b_k[m1];
        float* rp0 = out_res  + ((size_t)bB * NC + m0) * NT + bT;
        float* rp1 = out_res  + ((size_t)bB * NC + m1) * NT + bT;
        float* sp0 = out_skip + ((size_t)bB * NC + m0) * NT + bT;
        float* sp1 = out_skip + ((size_t)bB * NC + m1) * NT + bT;
        const float* xr0 = xb + (size_t)m0 * NT + bT;
        const float* xr1 = xb + (size_t)m1 * NT + bT;
#pragma unroll
        for (int nt = 0; nt < 8; nt++) {
            int n0 = nt * 8 + 2 * t;
            float2 xv0 = *(const float2*)(xr0 + n0);
            float2 xv1 = *(const float2*)(xr1 + n0);
            float2 rv0 = make_float2(xv0.x + accP[nt][0] + br0,
                                     xv0.y + accP[nt][1] + br0);
            float2 rv1 = make_float2(xv1.x + accP[nt][2] + br1,
                                     xv1.y + accP[nt][3] + br1);
            float2 sv0 = make_float2(accQ[nt][0] + bk0, accQ[nt][1] + bk0);
            float2 sv1 = make_float2(accQ[nt][2] + bk1, accQ[nt][3] + bk1);
            *(float2*)(rp0 + n0) = rv0;
            *(float2*)(rp1 + n0) = rv1;
            *(float2*)(sp0 + n0) = sv0;
            *(float2*)(sp1 + n0) = sv1;
        }
    }
}

extern "C" void kernel_launch(void* const* d_in, const int* in_sizes, int n_in,
                              void* d_out, int out_size) {
    const float* x  = (const float*)d_in[0];
    const float* wf = (const float*)d_in[1];
    const float* bf = (const float*)d_in[2];
    const float* wg = (const float*)d_in[3];
    const float* bg = (const float*)d_in[4];
    const float* wr = (const float*)d_in[5];
    const float* br = (const float*)d_in[6];
    const float* wk = (const float*)d_in[7];
    const float* bk = (const float*)d_in[8];
    float* out = (float*)d_out;

    cudaFuncSetAttribute(wavenet_mma_k,
                         cudaFuncAttributeMaxDynamicSharedMemorySize, SMEM_BYTES);

    prep_wA_k<<<768, 256>>>(wf, wg, wr, wk);
    wavenet_mma_k<<<dim3(NT / TT, NB), 512, SMEM_BYTES>>>(
        x, bf, bg, br, bk, out, out + (size_t)NB * NC * NT);
}